// round 1
// baseline (speedup 1.0000x reference)
#include <cuda_runtime.h>

// Attention_63324997812765 — fused QKV projection + causal softmax attention
// B=4, T=2048, E=1024, fp32. Round 0: fp32 tiled-SGEMM pipeline baseline.
//
// Pipeline:
//   1) proj_kernel x3 : QP/KP/VP = X @ W^T + b        (NT GEMM, 128x128x8 tiles)
//   2) scores_kernel  : S = QP @ KP^T * 1/32, lower-triangular tiles only
//   3) softmax_kernel : row-wise online softmax over j<=i, zero-fill padding
//   4) pv_kernel      : O = P @ VP with per-row-block K truncation (causal)

#define B_ 4
#define T_ 2048
#define E_ 1024
#define TS 128
#define KT 8
#define NTHREADS 256

// Scratch (device-global; no runtime allocation allowed).
__device__ float g_QP[B_ * T_ * E_];
__device__ float g_KP[B_ * T_ * E_];
__device__ float g_VP[B_ * T_ * E_];
__device__ float g_S[B_ * T_ * T_];

// ---------------------------------------------------------------------------
// NT GEMM with bias: Y[m,n] = bias[n] + sum_k X[m,k] * W[n,k]
// M = B*T = 8192, N = E, K = E. which selects QP/KP/VP output.
// ---------------------------------------------------------------------------
__global__ void __launch_bounds__(NTHREADS) proj_kernel(
    const float* __restrict__ X, const float* __restrict__ W,
    const float* __restrict__ bias, int which)
{
    float* Y = (which == 0) ? g_QP : ((which == 1) ? g_KP : g_VP);

    __shared__ float As[KT][TS + 4];
    __shared__ float Bs[KT][TS + 4];

    const int t  = threadIdx.x;
    const int bm = blockIdx.y, bn = blockIdx.x;
    const int tm = t >> 4, tn = t & 15;
    const int lr = t >> 1, lc = (t & 1) * 4;

    const float* Ag = X + (size_t)(bm * TS + lr) * E_ + lc;
    const float* Bg = W + (size_t)(bn * TS + lr) * E_ + lc;

    float acc[8][8] = {};

    for (int kt = 0; kt < E_; kt += KT) {
        float4 av = *(const float4*)(Ag + kt);
        float4 bv = *(const float4*)(Bg + kt);
        As[lc + 0][lr] = av.x; As[lc + 1][lr] = av.y;
        As[lc + 2][lr] = av.z; As[lc + 3][lr] = av.w;
        Bs[lc + 0][lr] = bv.x; Bs[lc + 1][lr] = bv.y;
        Bs[lc + 2][lr] = bv.z; Bs[lc + 3][lr] = bv.w;
        __syncthreads();
#pragma unroll
        for (int k = 0; k < KT; k++) {
            float a[8], b[8];
#pragma unroll
            for (int i = 0; i < 8; i++) a[i] = As[k][tm * 8 + i];
#pragma unroll
            for (int j = 0; j < 8; j++) b[j] = Bs[k][tn * 8 + j];
#pragma unroll
            for (int i = 0; i < 8; i++)
#pragma unroll
                for (int j = 0; j < 8; j++)
                    acc[i][j] = fmaf(a[i], b[j], acc[i][j]);
        }
        __syncthreads();
    }

#pragma unroll
    for (int i = 0; i < 8; i++) {
        const int m = bm * TS + tm * 8 + i;
#pragma unroll
        for (int j = 0; j < 8; j++) {
            const int n = bn * TS + tn * 8 + j;
            Y[(size_t)m * E_ + n] = acc[i][j] + bias[n];
        }
    }
}

// ---------------------------------------------------------------------------
// Scores: S[b,i,j] = (1/32) * sum_e QP[b,i,e] * KP[b,j,e]
// Only lower-triangular tiles (bn <= bm) when causal.
// ---------------------------------------------------------------------------
__global__ void __launch_bounds__(NTHREADS) scores_kernel(const int* __restrict__ causalp)
{
    const int bm = blockIdx.y, bn = blockIdx.x;
    if (*causalp && bn > bm) return;

    const int b = blockIdx.z;
    const float* A  = g_QP + (size_t)b * T_ * E_;
    const float* Bp = g_KP + (size_t)b * T_ * E_;
    float* S        = g_S  + (size_t)b * T_ * T_;

    __shared__ float As[KT][TS + 4];
    __shared__ float Bs[KT][TS + 4];

    const int t  = threadIdx.x;
    const int tm = t >> 4, tn = t & 15;
    const int lr = t >> 1, lc = (t & 1) * 4;

    const float* Ag = A  + (size_t)(bm * TS + lr) * E_ + lc;
    const float* Bg = Bp + (size_t)(bn * TS + lr) * E_ + lc;

    float acc[8][8] = {};

    for (int kt = 0; kt < E_; kt += KT) {
        float4 av = *(const float4*)(Ag + kt);
        float4 bv = *(const float4*)(Bg + kt);
        As[lc + 0][lr] = av.x; As[lc + 1][lr] = av.y;
        As[lc + 2][lr] = av.z; As[lc + 3][lr] = av.w;
        Bs[lc + 0][lr] = bv.x; Bs[lc + 1][lr] = bv.y;
        Bs[lc + 2][lr] = bv.z; Bs[lc + 3][lr] = bv.w;
        __syncthreads();
#pragma unroll
        for (int k = 0; k < KT; k++) {
            float a[8], b[8];
#pragma unroll
            for (int i = 0; i < 8; i++) a[i] = As[k][tm * 8 + i];
#pragma unroll
            for (int j = 0; j < 8; j++) b[j] = Bs[k][tn * 8 + j];
#pragma unroll
            for (int i = 0; i < 8; i++)
#pragma unroll
                for (int j = 0; j < 8; j++)
                    acc[i][j] = fmaf(a[i], b[j], acc[i][j]);
        }
        __syncthreads();
    }

    const float scale = 0.03125f;  // 1/sqrt(1024)
#pragma unroll
    for (int i = 0; i < 8; i++) {
        const int m = bm * TS + tm * 8 + i;
#pragma unroll
        for (int j = 0; j < 8; j++) {
            const int n = bn * TS + tn * 8 + j;
            S[(size_t)m * T_ + n] = acc[i][j] * scale;
        }
    }
}

// ---------------------------------------------------------------------------
// Row softmax over j in [0, jmax]; zero-fill (jmax, tile-end) so the PV GEMM
// can run full 128-row tiles without per-row masking.
// ---------------------------------------------------------------------------
__global__ void __launch_bounds__(NTHREADS) softmax_kernel(const int* __restrict__ causalp)
{
    const int b = blockIdx.y, i = blockIdx.x;
    float* row = g_S + ((size_t)b * T_ + i) * T_;
    const int causal = *causalp;
    const int jmax = causal ? i : (T_ - 1);
    const int t = threadIdx.x;

    __shared__ float red[NTHREADS];

    float lm = -3.4e38f;
    for (int j = t; j <= jmax; j += NTHREADS) lm = fmaxf(lm, row[j]);
    red[t] = lm; __syncthreads();
    for (int s = NTHREADS / 2; s > 0; s >>= 1) {
        if (t < s) red[t] = fmaxf(red[t], red[t + s]);
        __syncthreads();
    }
    const float m = red[0];
    __syncthreads();

    float ls = 0.f;
    for (int j = t; j <= jmax; j += NTHREADS) {
        float e = __expf(row[j] - m);
        row[j] = e;
        ls += e;
    }
    red[t] = ls; __syncthreads();
    for (int s = NTHREADS / 2; s > 0; s >>= 1) {
        if (t < s) red[t] += red[t + s];
        __syncthreads();
    }
    const float inv = 1.f / red[0];

    for (int j = t; j <= jmax; j += NTHREADS) row[j] *= inv;

    if (causal) {
        // Zero probabilities up to the end of this row's 128-row PV tile span.
        const int zend = ((i >> 7) + 1) << 7;  // <= T_
        for (int j = i + 1 + t; j < zend; j += NTHREADS) row[j] = 0.f;
    }
}

// ---------------------------------------------------------------------------
// NN GEMM: O[b,i,e] = sum_j P[b,i,j] * VP[b,j,e]
// Causal: K truncated at (bm+1)*128 (rows in tile see no later keys).
// ---------------------------------------------------------------------------
__global__ void __launch_bounds__(NTHREADS) pv_kernel(float* __restrict__ O,
                                                      const int* __restrict__ causalp)
{
    const int b = blockIdx.z;
    const int bm = blockIdx.y, bn = blockIdx.x;

    const float* A  = g_S  + (size_t)b * T_ * T_;
    const float* Bp = g_VP + (size_t)b * T_ * E_;
    float* C        = O    + (size_t)b * T_ * E_;

    const int Kend = (*causalp) ? (bm + 1) * TS : T_;

    __shared__ float As[KT][TS + 4];
    __shared__ float Bs[KT][TS + 4];

    const int t  = threadIdx.x;
    const int tm = t >> 4, tn = t & 15;
    const int lr = t >> 1, lc = (t & 1) * 4;
    const int kr = t >> 5, nc = (t & 31) * 4;

    const float* Ag = A  + (size_t)(bm * TS + lr) * T_ + lc;
    const float* Bg = Bp + (size_t)kr * E_ + bn * TS + nc;

    float acc[8][8] = {};

    for (int kt = 0; kt < Kend; kt += KT) {
        float4 av = *(const float4*)(Ag + kt);
        float4 bv = *(const float4*)(Bg + (size_t)kt * E_);
        As[lc + 0][lr] = av.x; As[lc + 1][lr] = av.y;
        As[lc + 2][lr] = av.z; As[lc + 3][lr] = av.w;
        *(float4*)&Bs[kr][nc] = bv;
        __syncthreads();
#pragma unroll
        for (int k = 0; k < KT; k++) {
            float a[8], bb[8];
#pragma unroll
            for (int i = 0; i < 8; i++) a[i] = As[k][tm * 8 + i];
#pragma unroll
            for (int j = 0; j < 8; j++) bb[j] = Bs[k][tn * 8 + j];
#pragma unroll
            for (int i = 0; i < 8; i++)
#pragma unroll
                for (int j = 0; j < 8; j++)
                    acc[i][j] = fmaf(a[i], bb[j], acc[i][j]);
        }
        __syncthreads();
    }

#pragma unroll
    for (int i = 0; i < 8; i++) {
        const int m = bm * TS + tm * 8 + i;
#pragma unroll
        for (int j = 0; j < 8; j++) {
            const int n = bn * TS + tn * 8 + j;
            C[(size_t)m * E_ + n] = acc[i][j];
        }
    }
}

// ---------------------------------------------------------------------------
extern "C" void kernel_launch(void* const* d_in, const int* in_sizes, int n_in,
                              void* d_out, int out_size)
{
    const float* q    = (const float*)d_in[0];
    const float* k    = (const float*)d_in[1];
    const float* v    = (const float*)d_in[2];
    const float* wq_w = (const float*)d_in[3];
    const float* wq_b = (const float*)d_in[4];
    const float* wk_w = (const float*)d_in[5];
    const float* wk_b = (const float*)d_in[6];
    const float* wv_w = (const float*)d_in[7];
    const float* wv_b = (const float*)d_in[8];
    const int* causal = (const int*)d_in[9];
    float* out = (float*)d_out;

    dim3 gp(E_ / TS, (B_ * T_) / TS);                 // 8 x 64
    proj_kernel<<<gp, NTHREADS>>>(q, wq_w, wq_b, 0);
    proj_kernel<<<gp, NTHREADS>>>(k, wk_w, wk_b, 1);
    proj_kernel<<<gp, NTHREADS>>>(v, wv_w, wv_b, 2);

    dim3 gs(T_ / TS, T_ / TS, B_);                    // 16 x 16 x 4
    scores_kernel<<<gs, NTHREADS>>>(causal);

    dim3 gm(T_, B_);                                  // 2048 x 4
    softmax_kernel<<<gm, NTHREADS>>>(causal);

    dim3 gv(E_ / TS, T_ / TS, B_);                    // 8 x 16 x 4
    pv_kernel<<<gv, NTHREADS>>>(out, causal);
}

// round 3
// speedup vs baseline: 2.4428x; 2.4428x over previous
#include <cuda_runtime.h>
#include <cuda_bf16.h>
#include <cstdint>

// Attention_63324997812765 — R2: bf16x3-split GEMMs on mma.sync (HMMA).
// (tcgen05 PTX is rejected: harness compiles via compute_103 virtual arch,
//  which lacks the 'a' accelerated-feature set. mma.sync/ldmatrix/cp.async
//  are baseline-legal and still run on the tensor pipe.)

#define B_ 4
#define T_ 2048
#define E_ 1024
#define TS 128      // block tile M=N
#define KC 32       // K-chunk (bf16 elems)
#define NTH 256
#define ROWB 80     // smem row stride bytes (32 bf16 = 64B data + 16B pad)
#define MATB (128 * ROWB)          // 10240 B per matrix tile
#define STAGEB (4 * MATB)          // Ah, Al, Bh, Bl = 40960 B
#define DSMEM (2 * STAGEB)         // double buffered = 81920 B

// ---------------------------------------------------------------------------
__device__ __forceinline__ uint32_t smem_u32(const void* p) {
    uint32_t a;
    asm("{ .reg .u64 t; cvta.to.shared.u64 t, %1; cvt.u32.u64 %0, t; }" : "=r"(a) : "l"(p));
    return a;
}
__device__ __forceinline__ void cpasync16(uint32_t s, const void* g) {
    asm volatile("cp.async.cg.shared.global [%0], [%1], 16;" :: "r"(s), "l"(g));
}
__device__ __forceinline__ void cp_commit() { asm volatile("cp.async.commit_group;" ::: "memory"); }
__device__ __forceinline__ void cp_wait0()  { asm volatile("cp.async.wait_group 0;" ::: "memory"); }
__device__ __forceinline__ void cp_wait1()  { asm volatile("cp.async.wait_group 1;" ::: "memory"); }

__device__ __forceinline__ void ldsm4(uint32_t* r, uint32_t addr) {
    asm volatile("ldmatrix.sync.aligned.m8n8.x4.shared.b16 {%0,%1,%2,%3}, [%4];"
                 : "=r"(r[0]), "=r"(r[1]), "=r"(r[2]), "=r"(r[3]) : "r"(addr));
}
__device__ __forceinline__ void mma16816(float* c, const uint32_t* a, const uint32_t* b) {
    asm volatile(
        "mma.sync.aligned.m16n8k16.row.col.f32.bf16.bf16.f32 "
        "{%0,%1,%2,%3}, {%4,%5,%6,%7}, {%8,%9}, {%0,%1,%2,%3};"
        : "+f"(c[0]), "+f"(c[1]), "+f"(c[2]), "+f"(c[3])
        : "r"(a[0]), "r"(a[1]), "r"(a[2]), "r"(a[3]), "r"(b[0]), "r"(b[1]));
}

// ---------------------------------------------------------------------------
// Device-global scratch
// ---------------------------------------------------------------------------
__device__ __nv_bfloat16 g_qhi[B_ * T_ * E_], g_qlo[B_ * T_ * E_];
__device__ __nv_bfloat16 g_khi[B_ * T_ * E_], g_klo[B_ * T_ * E_];
__device__ __nv_bfloat16 g_vhi[B_ * T_ * E_], g_vlo[B_ * T_ * E_];
__device__ __nv_bfloat16 g_wqhi[E_ * E_], g_wqlo[E_ * E_];
__device__ __nv_bfloat16 g_wkhi[E_ * E_], g_wklo[E_ * E_];
__device__ __nv_bfloat16 g_wvhi[E_ * E_], g_wvlo[E_ * E_];
__device__ __nv_bfloat16 g_QPhi[B_ * T_ * E_], g_QPlo[B_ * T_ * E_];
__device__ __nv_bfloat16 g_KPhi[B_ * T_ * E_], g_KPlo[B_ * T_ * E_];
__device__ __nv_bfloat16 g_VPthi[B_ * E_ * T_], g_VPtlo[B_ * E_ * T_];  // [b][e][t]
__device__ __nv_bfloat16 g_Phi[B_ * T_ * T_], g_Plo[B_ * T_ * T_];
__device__ float g_S[B_ * T_ * T_];

struct alignas(8) bf16x4 { __nv_bfloat16 v[4]; };

// ---------------------------------------------------------------------------
// fp32 -> (hi, lo) bf16 split
// ---------------------------------------------------------------------------
__global__ void __launch_bounds__(256) split_kernel(const float* __restrict__ x,
                                                    __nv_bfloat16* __restrict__ hi,
                                                    __nv_bfloat16* __restrict__ lo, int n4) {
    int i = blockIdx.x * 256 + threadIdx.x;
    if (i >= n4) return;
    float4 f = ((const float4*)x)[i];
    bf16x4 h, l;
    float v[4] = {f.x, f.y, f.z, f.w};
#pragma unroll
    for (int j = 0; j < 4; j++) {
        __nv_bfloat16 hb = __float2bfloat16(v[j]);
        h.v[j] = hb;
        l.v[j] = __float2bfloat16(v[j] - __bfloat162float(hb));
    }
    ((bf16x4*)hi)[i] = h;
    ((bf16x4*)lo)[i] = l;
}

// ---------------------------------------------------------------------------
// NT GEMM, bf16x3 split, mma.sync. D[128,128] per block.
// MODE 0: QP/KP proj: +bias -> hi/lo bf16 [m][E]
// MODE 1: V proj:     +bias -> hi/lo bf16 transposed [b][e][t]
// MODE 2: scores:     *1/32 -> fp32 S, skip bn>bm tiles when causal
// MODE 3: PV:                -> fp32 out, K truncated when causal
// ---------------------------------------------------------------------------
template <int MODE>
__global__ void __launch_bounds__(NTH)
gemm_bf16x3(const __nv_bfloat16* __restrict__ Ahi, const __nv_bfloat16* __restrict__ Alo,
            const __nv_bfloat16* __restrict__ Bhi, const __nv_bfloat16* __restrict__ Blo,
            int lda, int ldb, int Kdim,
            const float* __restrict__ bias,
            float* __restrict__ Of,
            __nv_bfloat16* __restrict__ Ohi, __nv_bfloat16* __restrict__ Olo,
            const int* __restrict__ causalp)
{
    const int bm = blockIdx.y, bn = blockIdx.x, bz = blockIdx.z;
    int causal = 0;
    if (MODE >= 2) causal = *causalp;
    if (MODE == 2 && causal && bn > bm) return;

    int Klen = Kdim;
    if (MODE == 3 && causal) Klen = (bm + 1) * TS;

    size_t aOff = 0, bOff = 0;
    if (MODE == 2) { aOff = (size_t)bz * T_ * E_; bOff = (size_t)bz * T_ * E_; }
    if (MODE == 3) { aOff = (size_t)bz * T_ * T_; bOff = (size_t)bz * E_ * T_; }
    const __nv_bfloat16* pAhi = Ahi + aOff;
    const __nv_bfloat16* pAlo = Alo + aOff;
    const __nv_bfloat16* pBhi = Bhi + bOff;
    const __nv_bfloat16* pBlo = Blo + bOff;

    extern __shared__ char dsm[];
    const uint32_t sbase = smem_u32(dsm);

    const int t = threadIdx.x;
    const int wid = t >> 5, lane = t & 31;
    const int wm = wid & 3, wn = wid >> 2;          // warp tile: rows wm*32, cols wn*64
    const int mrow0 = bm * TS, nrow0 = bn * TS;

    // cp.async mapping: thread -> (row, 2 of 4 16B segments)
    const int crow = t >> 1;
    const int cseg = (t & 1) * 2;
    const uint32_t cso = (uint32_t)(crow * ROWB + cseg * 16);

    // ldmatrix per-lane offsets
    const uint32_t aoff = (uint32_t)((lane & 15) * ROWB + (lane >> 4) * 16);
    const uint32_t boff = (uint32_t)((((lane & 7) + ((lane >> 1) & 8)) * ROWB) + (lane & 8) * 2);

    float acc[2][8][4] = {};

    const int nchunk = Klen / KC;

    // Prefetch chunk 0 into stage 0.
    {
        const int k0 = 0;
        const size_t ga = (size_t)(mrow0 + crow) * lda + k0 + cseg * 8;
        const size_t gb = (size_t)(nrow0 + crow) * ldb + k0 + cseg * 8;
        const uint32_t ss = sbase;
        cpasync16(ss + cso,                 pAhi + ga);
        cpasync16(ss + cso + 16,            pAhi + ga + 8);
        cpasync16(ss + MATB + cso,          pAlo + ga);
        cpasync16(ss + MATB + cso + 16,     pAlo + ga + 8);
        cpasync16(ss + 2 * MATB + cso,      pBhi + gb);
        cpasync16(ss + 2 * MATB + cso + 16, pBhi + gb + 8);
        cpasync16(ss + 3 * MATB + cso,      pBlo + gb);
        cpasync16(ss + 3 * MATB + cso + 16, pBlo + gb + 8);
        cp_commit();
    }

    for (int ch = 0; ch < nchunk; ch++) {
        const int s = ch & 1;
        const uint32_t ss = sbase + (uint32_t)s * STAGEB;

        if (ch + 1 < nchunk) {
            const int k0 = (ch + 1) * KC;
            const uint32_t sn = sbase + (uint32_t)((ch + 1) & 1) * STAGEB;
            const size_t ga = (size_t)(mrow0 + crow) * lda + k0 + cseg * 8;
            const size_t gb = (size_t)(nrow0 + crow) * ldb + k0 + cseg * 8;
            cpasync16(sn + cso,                 pAhi + ga);
            cpasync16(sn + cso + 16,            pAhi + ga + 8);
            cpasync16(sn + MATB + cso,          pAlo + ga);
            cpasync16(sn + MATB + cso + 16,     pAlo + ga + 8);
            cpasync16(sn + 2 * MATB + cso,      pBhi + gb);
            cpasync16(sn + 2 * MATB + cso + 16, pBhi + gb + 8);
            cpasync16(sn + 3 * MATB + cso,      pBlo + gb);
            cpasync16(sn + 3 * MATB + cso + 16, pBlo + gb + 8);
            cp_commit();
            cp_wait1();
        } else {
            cp_wait0();
        }
        __syncthreads();

        // Compute on stage s: 2 k16 steps.
#pragma unroll
        for (int k16 = 0; k16 < 2; k16++) {
            const uint32_t kb = (uint32_t)(k16 * 32);
            uint32_t ah[2][4], al[2][4], bh[4][4], bl[4][4];
#pragma unroll
            for (int mt = 0; mt < 2; mt++) {
                const uint32_t ra = ss + (uint32_t)((wm * 32 + mt * 16) * ROWB) + kb;
                ldsm4(ah[mt], ra + aoff);
                ldsm4(al[mt], ra + MATB + aoff);
            }
#pragma unroll
            for (int n2 = 0; n2 < 4; n2++) {
                const uint32_t rb = ss + 2 * MATB + (uint32_t)((wn * 64 + n2 * 16) * ROWB) + kb;
                ldsm4(bh[n2], rb + boff);
                ldsm4(bl[n2], rb + MATB + boff);
            }
#pragma unroll
            for (int mt = 0; mt < 2; mt++)
#pragma unroll
                for (int nt = 0; nt < 8; nt++) {
                    const int n2 = nt >> 1, hf = (nt & 1) * 2;
                    mma16816(acc[mt][nt], ah[mt], &bh[n2][hf]);
                    mma16816(acc[mt][nt], ah[mt], &bl[n2][hf]);
                    mma16816(acc[mt][nt], al[mt], &bh[n2][hf]);
                }
        }
        __syncthreads();
    }

    // ---------------- Epilogue ----------------
#pragma unroll
    for (int mt = 0; mt < 2; mt++) {
#pragma unroll
        for (int nt = 0; nt < 8; nt++) {
            const float* c = acc[mt][nt];
            const int row = bm * TS + wm * 32 + mt * 16 + (lane >> 2);
            const int col = bn * TS + wn * 64 + nt * 8 + (lane & 3) * 2;

            if constexpr (MODE == 0) {
                const float b0 = bias[col], b1 = bias[col + 1];
#pragma unroll
                for (int h = 0; h < 2; h++) {
                    const int r2 = row + h * 8;
                    const float v0 = c[h * 2 + 0] + b0, v1 = c[h * 2 + 1] + b1;
                    const __nv_bfloat16 h0 = __float2bfloat16(v0);
                    const __nv_bfloat16 h1 = __float2bfloat16(v1);
                    const __nv_bfloat16 l0 = __float2bfloat16(v0 - __bfloat162float(h0));
                    const __nv_bfloat16 l1 = __float2bfloat16(v1 - __bfloat162float(h1));
                    const size_t idx = (size_t)r2 * E_ + col;
                    *(__nv_bfloat162*)(Ohi + idx) = __halves2bfloat162(h0, h1);
                    *(__nv_bfloat162*)(Olo + idx) = __halves2bfloat162(l0, l1);
                }
            } else if constexpr (MODE == 1) {
                const float b0 = bias[col], b1 = bias[col + 1];
#pragma unroll
                for (int h = 0; h < 2; h++) {
                    const int r2 = row + h * 8;
                    const int bb = r2 >> 11, tok = r2 & (T_ - 1);
                    const float v0 = c[h * 2 + 0] + b0, v1 = c[h * 2 + 1] + b1;
                    const __nv_bfloat16 h0 = __float2bfloat16(v0);
                    const __nv_bfloat16 h1 = __float2bfloat16(v1);
                    const size_t i0 = ((size_t)bb * E_ + col) * T_ + tok;
                    const size_t i1 = i0 + T_;
                    Ohi[i0] = h0;
                    Ohi[i1] = h1;
                    Olo[i0] = __float2bfloat16(v0 - __bfloat162float(h0));
                    Olo[i1] = __float2bfloat16(v1 - __bfloat162float(h1));
                }
            } else if constexpr (MODE == 2) {
                const float sc = 0.03125f;
#pragma unroll
                for (int h = 0; h < 2; h++) {
                    const int r2 = row + h * 8;
                    float2 f = make_float2(c[h * 2 + 0] * sc, c[h * 2 + 1] * sc);
                    *(float2*)(Of + (size_t)bz * T_ * T_ + (size_t)r2 * T_ + col) = f;
                }
            } else {
#pragma unroll
                for (int h = 0; h < 2; h++) {
                    const int r2 = row + h * 8;
                    float2 f = make_float2(c[h * 2 + 0], c[h * 2 + 1]);
                    *(float2*)(Of + (size_t)bz * T_ * E_ + (size_t)r2 * E_ + col) = f;
                }
            }
        }
    }
}

// ---------------------------------------------------------------------------
// Row softmax on fp32 S -> hi/lo bf16 P, causal zero-fill to tile boundary.
// ---------------------------------------------------------------------------
__global__ void __launch_bounds__(NTH) softmax_kernel(const float* __restrict__ S,
                                                      __nv_bfloat16* __restrict__ Phi,
                                                      __nv_bfloat16* __restrict__ Plo,
                                                      const int* __restrict__ causalp)
{
    const int b = blockIdx.y, i = blockIdx.x;
    const float* row = S + ((size_t)b * T_ + i) * T_;
    __nv_bfloat16* ph = Phi + ((size_t)b * T_ + i) * T_;
    __nv_bfloat16* pl = Plo + ((size_t)b * T_ + i) * T_;
    const int causal = *causalp;
    const int jmax = causal ? i : (T_ - 1);
    const int t = threadIdx.x;

    __shared__ float red[NTH];

    float lm = -3.4e38f;
    for (int j = t; j <= jmax; j += NTH) lm = fmaxf(lm, row[j]);
    red[t] = lm; __syncthreads();
    for (int s = NTH / 2; s > 0; s >>= 1) {
        if (t < s) red[t] = fmaxf(red[t], red[t + s]);
        __syncthreads();
    }
    const float m = red[0];
    __syncthreads();

    float ls = 0.f;
    for (int j = t; j <= jmax; j += NTH) ls += __expf(row[j] - m);
    red[t] = ls; __syncthreads();
    for (int s = NTH / 2; s > 0; s >>= 1) {
        if (t < s) red[t] += red[t + s];
        __syncthreads();
    }
    const float inv = 1.f / red[0];

    for (int j = t; j <= jmax; j += NTH) {
        float p = __expf(row[j] - m) * inv;
        __nv_bfloat16 h = __float2bfloat16(p);
        ph[j] = h;
        pl[j] = __float2bfloat16(p - __bfloat162float(h));
    }
    if (causal) {
        const int zend = ((i >> 7) + 1) << 7;
        for (int j = i + 1 + t; j < zend; j += NTH) {
            ph[j] = __float2bfloat16(0.f);
            pl[j] = __float2bfloat16(0.f);
        }
    }
}

// ---------------------------------------------------------------------------
extern "C" void kernel_launch(void* const* d_in, const int* in_sizes, int n_in,
                              void* d_out, int out_size)
{
    const float* q    = (const float*)d_in[0];
    const float* k    = (const float*)d_in[1];
    const float* v    = (const float*)d_in[2];
    const float* wq_w = (const float*)d_in[3];
    const float* wq_b = (const float*)d_in[4];
    const float* wk_w = (const float*)d_in[5];
    const float* wk_b = (const float*)d_in[6];
    const float* wv_w = (const float*)d_in[7];
    const float* wv_b = (const float*)d_in[8];
    const int* causal = (const int*)d_in[9];
    float* out = (float*)d_out;

    void *qhi, *qlo, *khi, *klo, *vhi, *vlo;
    void *wqhi, *wqlo, *wkhi, *wklo, *wvhi, *wvlo;
    void *QPhi, *QPlo, *KPhi, *KPlo, *VPthi, *VPtlo, *Phi, *Plo, *Sp;
    cudaGetSymbolAddress(&qhi, g_qhi);   cudaGetSymbolAddress(&qlo, g_qlo);
    cudaGetSymbolAddress(&khi, g_khi);   cudaGetSymbolAddress(&klo, g_klo);
    cudaGetSymbolAddress(&vhi, g_vhi);   cudaGetSymbolAddress(&vlo, g_vlo);
    cudaGetSymbolAddress(&wqhi, g_wqhi); cudaGetSymbolAddress(&wqlo, g_wqlo);
    cudaGetSymbolAddress(&wkhi, g_wkhi); cudaGetSymbolAddress(&wklo, g_wklo);
    cudaGetSymbolAddress(&wvhi, g_wvhi); cudaGetSymbolAddress(&wvlo, g_wvlo);
    cudaGetSymbolAddress(&QPhi, g_QPhi); cudaGetSymbolAddress(&QPlo, g_QPlo);
    cudaGetSymbolAddress(&KPhi, g_KPhi); cudaGetSymbolAddress(&KPlo, g_KPlo);
    cudaGetSymbolAddress(&VPthi, g_VPthi); cudaGetSymbolAddress(&VPtlo, g_VPtlo);
    cudaGetSymbolAddress(&Phi, g_Phi);   cudaGetSymbolAddress(&Plo, g_Plo);
    cudaGetSymbolAddress(&Sp, g_S);

    cudaFuncSetAttribute(gemm_bf16x3<0>, cudaFuncAttributeMaxDynamicSharedMemorySize, DSMEM);
    cudaFuncSetAttribute(gemm_bf16x3<1>, cudaFuncAttributeMaxDynamicSharedMemorySize, DSMEM);
    cudaFuncSetAttribute(gemm_bf16x3<2>, cudaFuncAttributeMaxDynamicSharedMemorySize, DSMEM);
    cudaFuncSetAttribute(gemm_bf16x3<3>, cudaFuncAttributeMaxDynamicSharedMemorySize, DSMEM);

    // 1) hi/lo splits
    const int nQKV4 = B_ * T_ * E_ / 4, nW4 = E_ * E_ / 4;
    split_kernel<<<nQKV4 / 256, 256>>>(q, (__nv_bfloat16*)qhi, (__nv_bfloat16*)qlo, nQKV4);
    split_kernel<<<nQKV4 / 256, 256>>>(k, (__nv_bfloat16*)khi, (__nv_bfloat16*)klo, nQKV4);
    split_kernel<<<nQKV4 / 256, 256>>>(v, (__nv_bfloat16*)vhi, (__nv_bfloat16*)vlo, nQKV4);
    split_kernel<<<nW4 / 256, 256>>>(wq_w, (__nv_bfloat16*)wqhi, (__nv_bfloat16*)wqlo, nW4);
    split_kernel<<<nW4 / 256, 256>>>(wk_w, (__nv_bfloat16*)wkhi, (__nv_bfloat16*)wklo, nW4);
    split_kernel<<<nW4 / 256, 256>>>(wv_w, (__nv_bfloat16*)wvhi, (__nv_bfloat16*)wvlo, nW4);

    // 2) Projections
    dim3 gp(E_ / TS, (B_ * T_) / TS, 1);  // 8 x 64
    gemm_bf16x3<0><<<gp, NTH, DSMEM>>>((__nv_bfloat16*)qhi, (__nv_bfloat16*)qlo,
                                       (__nv_bfloat16*)wqhi, (__nv_bfloat16*)wqlo,
                                       E_, E_, E_, wq_b, nullptr,
                                       (__nv_bfloat16*)QPhi, (__nv_bfloat16*)QPlo, nullptr);
    gemm_bf16x3<0><<<gp, NTH, DSMEM>>>((__nv_bfloat16*)khi, (__nv_bfloat16*)klo,
                                       (__nv_bfloat16*)wkhi, (__nv_bfloat16*)wklo,
                                       E_, E_, E_, wk_b, nullptr,
                                       (__nv_bfloat16*)KPhi, (__nv_bfloat16*)KPlo, nullptr);
    gemm_bf16x3<1><<<gp, NTH, DSMEM>>>((__nv_bfloat16*)vhi, (__nv_bfloat16*)vlo,
                                       (__nv_bfloat16*)wvhi, (__nv_bfloat16*)wvlo,
                                       E_, E_, E_, wv_b, nullptr,
                                       (__nv_bfloat16*)VPthi, (__nv_bfloat16*)VPtlo, nullptr);

    // 3) Scores (lower-triangular tiles)
    dim3 gs(T_ / TS, T_ / TS, B_);
    gemm_bf16x3<2><<<gs, NTH, DSMEM>>>((__nv_bfloat16*)QPhi, (__nv_bfloat16*)QPlo,
                                       (__nv_bfloat16*)KPhi, (__nv_bfloat16*)KPlo,
                                       E_, E_, E_, nullptr, (float*)Sp,
                                       nullptr, nullptr, causal);

    // 4) Softmax -> P hi/lo
    dim3 gm(T_, B_);
    softmax_kernel<<<gm, NTH>>>((const float*)Sp, (__nv_bfloat16*)Phi, (__nv_bfloat16*)Plo, causal);

    // 5) O = P @ VPt^T (causal K truncation)
    dim3 gv(E_ / TS, T_ / TS, B_);
    gemm_bf16x3<3><<<gv, NTH, DSMEM>>>((__nv_bfloat16*)Phi, (__nv_bfloat16*)Plo,
                                       (__nv_bfloat16*)VPthi, (__nv_bfloat16*)VPtlo,
                                       T_, T_, T_, nullptr, out,
                                       nullptr, nullptr, causal);
}